// round 12
// baseline (speedup 1.0000x reference)
#include <cuda_runtime.h>
#include <stdint.h>
#include <math.h>

#define BATCH 512
#define OUTF  1024
#define KPOS  256
#define NIDX  4096
#define BTILE 4
#define KQ    4
#define KQLEN 64
#define SLOT  16384                               // NIDX * BTILE
#define SMEM_SZ (3 * SLOT + KQLEN * 8)            // 49664 B

// ---- device scratch (no allocations allowed) ----
__device__ uint8_t  g_tab[NIDX * NIDX];           // 16MB compact u8 table
__device__ ushort4  g_w4[(KPOS / 4) * OUTF];      // PRE-SWIZZLED 4B offsets [kb][o]
__device__ uint2    g_part[128 * OUTF * KQ];      // partials per (bg,o,kq): 4MB

// swizzle: XOR bits[4:5] with bits[7:8]; bijective within a 16KB slot
__device__ __forceinline__ uint32_t sw(uint32_t a) {
    return a ^ ((a >> 3) & 0x30u);
}

// -------- fused pre-pass: detect mode + convert table + prep w offsets ------
// Mode is computed per-block from the SAME first 256 words -> identical verdict
// in every block (deterministic), no separate serializing kernel.
__global__ __launch_bounds__(256) void convert_all_kernel(
    const void* __restrict__ table, const int* __restrict__ w_idx) {
    const uint32_t* tw = (const uint32_t*)table;
    int lane = threadIdx.x & 31;
    bool small = true, isf = true;
#pragma unroll
    for (int i = 0; i < 8; i++) {
        uint32_t x = tw[lane + i * 32];
        small = small && (x < 256u);
        float f = __uint_as_float(x);
        isf = isf && (f >= 0.0f) && (f < 256.0f) && (f == truncf(f));
    }
    small = __all_sync(0xFFFFFFFFu, small);
    isf   = __all_sync(0xFFFFFFFFu, isf);
    const int mode = small ? 1 : (isf ? 2 : 0);

    const int t = blockIdx.x * blockDim.x + threadIdx.x;  // 1M threads

    // prep_w for the first 64K threads
    if (t < (KPOS / 4) * OUTF) {
        int kb = t >> 10;
        int o  = t & 1023;
        int4 v = *(const int4*)&w_idx[o * KPOS + kb * 4];
        uint32_t a = (uint32_t)(v.x < 0 ? 0 : (v.x > NIDX - 1 ? NIDX - 1 : v.x)) * 4u;
        uint32_t b = (uint32_t)(v.y < 0 ? 0 : (v.y > NIDX - 1 ? NIDX - 1 : v.y)) * 4u;
        uint32_t c = (uint32_t)(v.z < 0 ? 0 : (v.z > NIDX - 1 ? NIDX - 1 : v.z)) * 4u;
        uint32_t d = (uint32_t)(v.w < 0 ? 0 : (v.w > NIDX - 1 ? NIDX - 1 : v.w)) * 4u;
        g_w4[t] = make_ushort4((uint16_t)sw(a), (uint16_t)sw(b),
                               (uint16_t)sw(c), (uint16_t)sw(d));
    }

    // convert 16 bytes
    uint4 o;
    if (mode == 1) {
        const int4* src = (const int4*)table;
        uint32_t p[4];
#pragma unroll
        for (int s = 0; s < 4; s++) {
            int4 v = src[t * 4 + s];
            p[s] = (uint32_t)(v.x & 255) | ((uint32_t)(v.y & 255) << 8) |
                   ((uint32_t)(v.z & 255) << 16) | ((uint32_t)(v.w & 255) << 24);
        }
        o = make_uint4(p[0], p[1], p[2], p[3]);
    } else if (mode == 2) {
        const float4* src = (const float4*)table;
        uint32_t p[4];
#pragma unroll
        for (int s = 0; s < 4; s++) {
            float4 v = src[t * 4 + s];
            p[s] = (uint32_t)v.x | ((uint32_t)v.y << 8) |
                   ((uint32_t)v.z << 16) | ((uint32_t)v.w << 24);
        }
        o = make_uint4(p[0], p[1], p[2], p[3]);
    } else {
        o = ((const uint4*)table)[t];
    }
    *(uint4*)&g_tab[t * 16] = o;
}

// transpose 4 rows x 16B -> interleaved entries buf[w*4+j] (swizzled addrs)
__device__ __forceinline__ void transpose_store(uint8_t* bufp, const uint32_t* sa,
                                                const uint4* q) {
#pragma unroll
    for (int s = 0; s < 4; s++) {
        uint32_t r0 = ((const uint32_t*)&q[0])[s];
        uint32_t r1 = ((const uint32_t*)&q[1])[s];
        uint32_t r2 = ((const uint32_t*)&q[2])[s];
        uint32_t r3 = ((const uint32_t*)&q[3])[s];
        uint32_t t0 = __byte_perm(r0, r1, 0x5140);
        uint32_t t1 = __byte_perm(r0, r1, 0x7362);
        uint32_t t2 = __byte_perm(r2, r3, 0x5140);
        uint32_t t3 = __byte_perm(r2, r3, 0x7362);
        uint4 o4;
        o4.x = __byte_perm(t0, t2, 0x5410);
        o4.y = __byte_perm(t0, t2, 0x7632);
        o4.z = __byte_perm(t1, t3, 0x5410);
        o4.w = __byte_perm(t1, t3, 0x7632);
        *(uint4*)(bufp + sa[s]) = o4;
    }
}

// -------- main kernel --------
// CTA = 256 thr, 4 batches x 1024 outputs (4/thread) x quarter of the k's.
// 4 CTAs/SM -> 4 independent barrier domains. 3-slot ring, 1 barrier per k:
// interval k gathers k (slot sg), stores k+1 (preloaded at interval k-1 -> one
// full barrier of latency cover), then preloads k+2.
__global__ __launch_bounds__(256, 4)
void lookup_kernel(const int* __restrict__ in_idx) {
    extern __shared__ __align__(16) uint8_t smem[];
    ushort4* iid = (ushort4*)(smem + 3 * SLOT);   // [KQLEN] packed row indices

    const int tid = threadIdx.x;
    const int bg  = blockIdx.x >> 2;
    const int kq  = blockIdx.x & 3;
    const int b0  = bg * BTILE;
    const uint4* tab128 = (const uint4*)g_tab;

    // stage this quarter's input indices (clamped): t = j*64 + kk
    {
        int j = tid >> 6, kk = tid & 63;
        int v = in_idx[(b0 + j) * KPOS + kq * KQLEN + kk];
        v = v < 0 ? 0 : (v > NIDX - 1 ? NIDX - 1 : v);
        *((uint16_t*)&iid[kk] + j) = (uint16_t)v;
    }

    // precomputed swizzled store addresses (thread owns chunk l = tid)
    uint32_t sa[4];
#pragma unroll
    for (int s = 0; s < 4; s++) sa[s] = sw(64u * (uint32_t)tid + 16u * s);

    __syncthreads();

    // ---- prologue: store k=0 into slot 0, preload q <- k=1 ----
    uint4 q[4];
    {
        ushort4 iv = iid[0];
        uint32_t r[4] = {iv.x, iv.y, iv.z, iv.w};
#pragma unroll
        for (int j = 0; j < 4; j++) q[j] = tab128[r[j] * 256 + tid];
        transpose_store(smem, sa, q);
        ushort4 iv2 = iid[1];
        uint32_t r2[4] = {iv2.x, iv2.y, iv2.z, iv2.w};
#pragma unroll
        for (int j = 0; j < 4; j++) q[j] = tab128[r2[j] * 256 + tid];
    }
    __syncthreads();

    uint32_t aLo[4] = {0, 0, 0, 0};   // outputs o = tid + 256*m
    uint32_t aHi[4] = {0, 0, 0, 0};

    int sg = 0;                        // slot of current gather k
    for (int kb = 0; kb < KQLEN / 4; kb++) {
        const int gkb = kq * (KQLEN / 4) + kb;
        ushort4 w4[4];
#pragma unroll
        for (int m = 0; m < 4; m++)
            w4[m] = g_w4[gkb * OUTF + tid + 256 * m];  // pre-swizzled offsets
        const uint16_t* wv = (const uint16_t*)w4;       // wv[m*4+u]
#pragma unroll
        for (int u = 0; u < 4; u++) {
            const int k  = kb * 4 + u;
            const int ns = (sg == 2) ? 0 : sg + 1;      // slot of k+1
            // gather k for 4 outputs (independent of q)
            const uint8_t* bp = smem + sg * SLOT;
#pragma unroll
            for (int m = 0; m < 4; m++) {
                uint32_t v = *(const uint32_t*)(bp + wv[m * 4 + u]);
                aLo[m] = __vadd2(aLo[m], __byte_perm(v, 0, 0x4140));
                aHi[m] = __vadd2(aHi[m], __byte_perm(v, 0, 0x4342));
            }
            // store k+1 (preloaded last interval), then preload k+2
            if (k + 1 < KQLEN)
                transpose_store(smem + ns * SLOT, sa, q);
            if (k + 2 < KQLEN) {
                ushort4 iv = iid[k + 2];
                uint32_t r[4] = {iv.x, iv.y, iv.z, iv.w};
#pragma unroll
                for (int j = 0; j < 4; j++) q[j] = tab128[r[j] * 256 + tid];
            }
            __syncthreads();
            sg = ns;
        }
    }

    // ---- write packed u16 partials (disjoint per kq; no atomics) ----
#pragma unroll
    for (int m = 0; m < 4; m++)
        g_part[(uint32_t)(bg * OUTF + tid + 256 * m) * 4u + kq] =
            make_uint2(aLo[m], aHi[m]);
}

// -------- reduce: sum 4 k-quarters, dequantize, write out --------
__global__ __launch_bounds__(256)
void reduce_kernel(const float* __restrict__ scale_p,
                   const float* __restrict__ zp_p,
                   float* __restrict__ out) {
    int t  = blockIdx.x * blockDim.x + threadIdx.x;   // 128*1024
    int bg = t >> 10;
    int o  = t & 1023;
    const uint4* pp = (const uint4*)&g_part[(uint32_t)(bg * OUTF + o) * 4u];
    uint4 p01 = pp[0], p23 = pp[1];                   // 2x LDG.128
    uint32_t Lo = __vadd2(__vadd2(p01.x, p01.z), __vadd2(p23.x, p23.z));
    uint32_t Hi = __vadd2(__vadd2(p01.y, p01.w), __vadd2(p23.y, p23.w));
    const float scale = *scale_p;
    const float zp    = *zp_p;
    const float bias  = 256.0f * zp;
    int b0 = bg * BTILE;
    out[(b0 + 0) * OUTF + o] = ((float)(Lo & 0xFFFFu) - bias) * scale;
    out[(b0 + 1) * OUTF + o] = ((float)(Lo >> 16)     - bias) * scale;
    out[(b0 + 2) * OUTF + o] = ((float)(Hi & 0xFFFFu) - bias) * scale;
    out[(b0 + 3) * OUTF + o] = ((float)(Hi >> 16)     - bias) * scale;
}

extern "C" void kernel_launch(void* const* d_in, const int* in_sizes, int n_in,
                              void* d_out, int out_size) {
    (void)in_sizes; (void)n_in; (void)out_size;
    const int*   in_idx = (const int*)d_in[0];
    const int*   w_idx  = (const int*)d_in[1];
    const void*  table  = (const void*)d_in[2];
    const float* scale  = (const float*)d_in[3];
    const float* zp     = (const float*)d_in[4];
    float*       outp   = (float*)d_out;

    // Not stream-ordered; safe on every call (incl. during graph capture).
    cudaFuncSetAttribute(lookup_kernel,
                         cudaFuncAttributeMaxDynamicSharedMemorySize, SMEM_SZ);

    convert_all_kernel<<<(NIDX * NIDX / 16) / 256, 256>>>(table, w_idx);
    lookup_kernel<<<128 * KQ, 256, SMEM_SZ>>>(in_idx);
    reduce_kernel<<<(128 * OUTF) / 256, 256>>>(scale, zp, outp);
}

// round 15
// speedup vs baseline: 1.1356x; 1.1356x over previous
#include <cuda_runtime.h>
#include <stdint.h>
#include <math.h>

#define BATCH 512
#define OUTF  1024
#define KPOS  256
#define NIDX  4096
#define BTILE 4
#define KQ    8
#define KQLEN 32
#define NBG   128
#define SLOT  16384                               // NIDX * BTILE
#define SMEM_SZ (3 * SLOT + KQLEN * 8)            // 49408 B

// ---- device scratch (no allocations allowed) ----
__device__ uint8_t  g_tab[NIDX * NIDX];           // 16MB compact u8 table
__device__ ushort4  g_w4[(KPOS / 4) * OUTF];      // PRE-SWIZZLED 4B offsets [kb][o]
__device__ uint2    g_part[KQ * NBG * OUTF];      // partials [kq][bg][o]: 8MB
__device__ int      g_pad;                        // (layout spacer)

// swizzle: XOR bits[4:5] with bits[7:8]; bijective within a 16KB slot
__device__ __forceinline__ uint32_t sw(uint32_t a) {
    return a ^ ((a >> 3) & 0x30u);
}

// -------- fused pre-pass: detect mode + convert table + prep w offsets ------
// Mode computed per-block from the SAME first 256 words -> identical verdict
// everywhere (deterministic), no serializing detect kernel.
__global__ __launch_bounds__(256) void convert_all_kernel(
    const void* __restrict__ table, const int* __restrict__ w_idx) {
    const uint32_t* tw = (const uint32_t*)table;
    int lane = threadIdx.x & 31;
    bool small = true, isf = true;
#pragma unroll
    for (int i = 0; i < 8; i++) {
        uint32_t x = tw[lane + i * 32];
        small = small && (x < 256u);
        float f = __uint_as_float(x);
        isf = isf && (f >= 0.0f) && (f < 256.0f) && (f == truncf(f));
    }
    small = __all_sync(0xFFFFFFFFu, small);
    isf   = __all_sync(0xFFFFFFFFu, isf);
    const int mode = small ? 1 : (isf ? 2 : 0);

    const int t = blockIdx.x * blockDim.x + threadIdx.x;  // 1M threads

    // prep_w for the first 64K threads
    if (t < (KPOS / 4) * OUTF) {
        int kb = t >> 10;
        int o  = t & 1023;
        int4 v = *(const int4*)&w_idx[o * KPOS + kb * 4];
        uint32_t a = (uint32_t)(v.x < 0 ? 0 : (v.x > NIDX - 1 ? NIDX - 1 : v.x)) * 4u;
        uint32_t b = (uint32_t)(v.y < 0 ? 0 : (v.y > NIDX - 1 ? NIDX - 1 : v.y)) * 4u;
        uint32_t c = (uint32_t)(v.z < 0 ? 0 : (v.z > NIDX - 1 ? NIDX - 1 : v.z)) * 4u;
        uint32_t d = (uint32_t)(v.w < 0 ? 0 : (v.w > NIDX - 1 ? NIDX - 1 : v.w)) * 4u;
        g_w4[t] = make_ushort4((uint16_t)sw(a), (uint16_t)sw(b),
                               (uint16_t)sw(c), (uint16_t)sw(d));
    }

    // convert 16 bytes
    uint4 o;
    if (mode == 1) {
        const int4* src = (const int4*)table;
        uint32_t p[4];
#pragma unroll
        for (int s = 0; s < 4; s++) {
            int4 v = src[t * 4 + s];
            p[s] = (uint32_t)(v.x & 255) | ((uint32_t)(v.y & 255) << 8) |
                   ((uint32_t)(v.z & 255) << 16) | ((uint32_t)(v.w & 255) << 24);
        }
        o = make_uint4(p[0], p[1], p[2], p[3]);
    } else if (mode == 2) {
        const float4* src = (const float4*)table;
        uint32_t p[4];
#pragma unroll
        for (int s = 0; s < 4; s++) {
            float4 v = src[t * 4 + s];
            p[s] = (uint32_t)v.x | ((uint32_t)v.y << 8) |
                   ((uint32_t)v.z << 16) | ((uint32_t)v.w << 24);
        }
        o = make_uint4(p[0], p[1], p[2], p[3]);
    } else {
        o = ((const uint4*)table)[t];
    }
    *(uint4*)&g_tab[t * 16] = o;
}

// transpose 4 rows x 16B -> interleaved entries buf[w*4+j] (swizzled addrs)
__device__ __forceinline__ void transpose_store(uint8_t* bufp, const uint32_t* sa,
                                                const uint4* q) {
#pragma unroll
    for (int s = 0; s < 4; s++) {
        uint32_t r0 = ((const uint32_t*)&q[0])[s];
        uint32_t r1 = ((const uint32_t*)&q[1])[s];
        uint32_t r2 = ((const uint32_t*)&q[2])[s];
        uint32_t r3 = ((const uint32_t*)&q[3])[s];
        uint32_t t0 = __byte_perm(r0, r1, 0x5140);
        uint32_t t1 = __byte_perm(r0, r1, 0x7362);
        uint32_t t2 = __byte_perm(r2, r3, 0x5140);
        uint32_t t3 = __byte_perm(r2, r3, 0x7362);
        uint4 o4;
        o4.x = __byte_perm(t0, t2, 0x5410);
        o4.y = __byte_perm(t0, t2, 0x7632);
        o4.z = __byte_perm(t1, t3, 0x5410);
        o4.w = __byte_perm(t1, t3, 0x7632);
        *(uint4*)(bufp + sa[s]) = o4;
    }
}

// -------- main kernel --------
// CTA = 256 thr, 4 batches x 1024 outputs (4/thread) x 32 k's. Grid = 1024
// CTAs at 4/SM -> ~1.7 waves with dynamic refill, amortizing the partial-wave
// imbalance of a 512-CTA single wave. 3-slot ring, 1 barrier per k: gather k
// (slot sg), store k+1 (preloaded last interval), preload k+2.
__global__ __launch_bounds__(256, 4)
void lookup_kernel(const int* __restrict__ in_idx) {
    extern __shared__ __align__(16) uint8_t smem[];
    ushort4* iid = (ushort4*)(smem + 3 * SLOT);   // [KQLEN] packed row indices

    const int tid = threadIdx.x;
    const int bg  = blockIdx.x >> 3;
    const int kq  = blockIdx.x & 7;
    const int b0  = bg * BTILE;
    const uint4* tab128 = (const uint4*)g_tab;

    // stage this chunk's input indices (clamped): t = j*64 + kk, kk<32 active
    {
        int j = tid >> 6, kk = tid & 63;
        if (kk < KQLEN) {
            int v = in_idx[(b0 + j) * KPOS + kq * KQLEN + kk];
            v = v < 0 ? 0 : (v > NIDX - 1 ? NIDX - 1 : v);
            *((uint16_t*)&iid[kk] + j) = (uint16_t)v;
        }
    }

    // precomputed swizzled store addresses (thread owns chunk l = tid)
    uint32_t sa[4];
#pragma unroll
    for (int s = 0; s < 4; s++) sa[s] = sw(64u * (uint32_t)tid + 16u * s);

    __syncthreads();

    // ---- prologue: store k=0 into slot 0, preload q <- k=1 ----
    uint4 q[4];
    {
        ushort4 iv = iid[0];
        uint32_t r[4] = {iv.x, iv.y, iv.z, iv.w};
#pragma unroll
        for (int j = 0; j < 4; j++) q[j] = tab128[r[j] * 256 + tid];
        transpose_store(smem, sa, q);
        ushort4 iv2 = iid[1];
        uint32_t r2[4] = {iv2.x, iv2.y, iv2.z, iv2.w};
#pragma unroll
        for (int j = 0; j < 4; j++) q[j] = tab128[r2[j] * 256 + tid];
    }
    __syncthreads();

    uint32_t aLo[4] = {0, 0, 0, 0};   // outputs o = tid + 256*m
    uint32_t aHi[4] = {0, 0, 0, 0};

    int sg = 0;                        // slot of current gather k
    for (int kb = 0; kb < KQLEN / 4; kb++) {
        const int gkb = kq * (KQLEN / 4) + kb;
        ushort4 w4[4];
#pragma unroll
        for (int m = 0; m < 4; m++)
            w4[m] = g_w4[gkb * OUTF + tid + 256 * m];  // pre-swizzled offsets
        const uint16_t* wv = (const uint16_t*)w4;       // wv[m*4+u]
#pragma unroll
        for (int u = 0; u < 4; u++) {
            const int k  = kb * 4 + u;
            const int ns = (sg == 2) ? 0 : sg + 1;      // slot of k+1
            // gather k for 4 outputs (independent of q)
            const uint8_t* bp = smem + sg * SLOT;
#pragma unroll
            for (int m = 0; m < 4; m++) {
                uint32_t v = *(const uint32_t*)(bp + wv[m * 4 + u]);
                aLo[m] = __vadd2(aLo[m], __byte_perm(v, 0, 0x4140));
                aHi[m] = __vadd2(aHi[m], __byte_perm(v, 0, 0x4342));
            }
            // store k+1 (preloaded last interval), then preload k+2
            if (k + 1 < KQLEN)
                transpose_store(smem + ns * SLOT, sa, q);
            if (k + 2 < KQLEN) {
                ushort4 iv = iid[k + 2];
                uint32_t r[4] = {iv.x, iv.y, iv.z, iv.w};
#pragma unroll
                for (int j = 0; j < 4; j++) q[j] = tab128[r[j] * 256 + tid];
            }
            __syncthreads();
            sg = ns;
        }
    }

    // ---- write packed u16 partials, [kq][bg][o] layout: fully coalesced ----
    uint2* pbase = &g_part[(uint32_t)kq * (NBG * OUTF) + (uint32_t)bg * OUTF];
#pragma unroll
    for (int m = 0; m < 4; m++)
        pbase[tid + 256 * m] = make_uint2(aLo[m], aHi[m]);
}

// -------- reduce: sum 8 k-chunks, dequantize, write out --------
__global__ __launch_bounds__(256)
void reduce_kernel(const float* __restrict__ scale_p,
                   const float* __restrict__ zp_p,
                   float* __restrict__ out) {
    int t  = blockIdx.x * blockDim.x + threadIdx.x;   // 128*1024
    int bg = t >> 10;
    int o  = t & 1023;
    uint32_t Lo = 0, Hi = 0;
#pragma unroll
    for (int kq = 0; kq < KQ; kq++) {
        uint2 p = g_part[(uint32_t)kq * (NBG * OUTF) + (uint32_t)bg * OUTF + o];
        Lo = __vadd2(Lo, p.x);    // u16 sums <= 65280, no overflow
        Hi = __vadd2(Hi, p.y);
    }
    const float scale = *scale_p;
    const float zp    = *zp_p;
    const float bias  = 256.0f * zp;
    int b0 = bg * BTILE;
    out[(b0 + 0) * OUTF + o] = ((float)(Lo & 0xFFFFu) - bias) * scale;
    out[(b0 + 1) * OUTF + o] = ((float)(Lo >> 16)     - bias) * scale;
    out[(b0 + 2) * OUTF + o] = ((float)(Hi & 0xFFFFu) - bias) * scale;
    out[(b0 + 3) * OUTF + o] = ((float)(Hi >> 16)     - bias) * scale;
}

extern "C" void kernel_launch(void* const* d_in, const int* in_sizes, int n_in,
                              void* d_out, int out_size) {
    (void)in_sizes; (void)n_in; (void)out_size;
    const int*   in_idx = (const int*)d_in[0];
    const int*   w_idx  = (const int*)d_in[1];
    const void*  table  = (const void*)d_in[2];
    const float* scale  = (const float*)d_in[3];
    const float* zp     = (const float*)d_in[4];
    float*       outp   = (float*)d_out;

    // Not stream-ordered; safe on every call (incl. during graph capture).
    cudaFuncSetAttribute(lookup_kernel,
                         cudaFuncAttributeMaxDynamicSharedMemorySize, SMEM_SZ);

    convert_all_kernel<<<(NIDX * NIDX / 16) / 256, 256>>>(table, w_idx);
    lookup_kernel<<<NBG * KQ, 256, SMEM_SZ>>>(in_idx);
    reduce_kernel<<<(NBG * OUTF) / 256, 256>>>(scale, zp, outp);
}